// round 6
// baseline (speedup 1.0000x reference)
#include <cuda_runtime.h>
#include <math.h>
#include <stdint.h>

#define SEQ    128
#define NB     64
#define VOCAB  10000
#define HDIM   1024
#define M1     (SEQ * NB)          /* 8192 */
#define NCTA_REC 128

// ---------------- static device scratch (no allocation allowed) ------------
__device__ float g_X1[(size_t)M1 * HDIM];      // emb[tok]@Wx0 + b0 for all steps (32 MB)
__device__ float g_H2[(size_t)M1 * HDIM];      // layer-2 hidden trajectory (32 MB)
__device__ float g_h1[2][NB * HDIM];           // ping-pong layer-1 state
__device__ float g_h2[2][NB * HDIM];           // ping-pong layer-2 state
__device__ unsigned g_bar_count;
__device__ volatile unsigned g_bar_gen;

// ---------------- grid-wide barrier (all 128 CTAs resident) ----------------
__device__ __forceinline__ void grid_bar() {
    __threadfence();                       // publish this thread's global writes
    __syncthreads();
    if (threadIdx.x == 0) {
        unsigned gen = g_bar_gen;
        if (atomicAdd(&g_bar_count, 1u) == NCTA_REC - 1) {
            g_bar_count = 0;
            __threadfence();
            g_bar_gen = gen + 1;           // release
        } else {
            while (g_bar_gen == gen) { __nanosleep(40); }
            __threadfence();               // acquire: invalidate L1 before consuming
        }
    }
    __syncthreads();
}

// ===========================================================================
// Kernel 1:  X1[m][n] = emb[tok[m]][:] @ Wx0[:][n] + b0[n]
//            M=8192, N=1024, K=1024.  128x128x16 tiles, 256 thr, 8x8 micro.
//            A (emb rows) is K-contiguous -> transposed into smem [k][m].
//            B (Wx0) is [k][n] row-major -> stored directly.
// ===========================================================================
__global__ void __launch_bounds__(256) k_x1(
    const int*   __restrict__ tok,
    const float* __restrict__ emb,
    const float* __restrict__ Wx0,
    const float* __restrict__ b0)
{
    __shared__ float As[16][132];   // [k][m]
    __shared__ float Bs[16][132];   // [k][n]
    __shared__ int   stok[128];

    const int tid   = threadIdx.x;
    const int mbase = blockIdx.y << 7;
    const int nbase = blockIdx.x << 7;

    if (tid < 128) stok[tid] = tok[mbase + tid];
    __syncthreads();

    const int lrow = tid >> 2;             // 0..63  (A rows lrow, lrow+64)
    const int lkq  = (tid & 3) << 2;       // 0,4,8,12
    const int bk   = tid >> 5;             // 0..7   (B rows bk, bk+8)
    const int bnq  = (tid & 31) << 2;      // 0..124

    const float* a0p = emb + (size_t)stok[lrow]      * HDIM + lkq;
    const float* a1p = emb + (size_t)stok[lrow + 64] * HDIM + lkq;

    float acc[8][8];
    #pragma unroll
    for (int r = 0; r < 8; r++)
        #pragma unroll
        for (int c = 0; c < 8; c++) acc[r][c] = 0.f;

    float4 pa0 = *(const float4*)a0p;
    float4 pa1 = *(const float4*)a1p;
    float4 pb0 = *(const float4*)(Wx0 + (size_t)bk       * HDIM + nbase + bnq);
    float4 pb1 = *(const float4*)(Wx0 + (size_t)(bk + 8) * HDIM + nbase + bnq);

    const int tx = tid & 15, ty = tid >> 4;

    for (int k0 = 0; k0 < HDIM; k0 += 16) {
        As[lkq + 0][lrow]      = pa0.x;  As[lkq + 1][lrow]      = pa0.y;
        As[lkq + 2][lrow]      = pa0.z;  As[lkq + 3][lrow]      = pa0.w;
        As[lkq + 0][lrow + 64] = pa1.x;  As[lkq + 1][lrow + 64] = pa1.y;
        As[lkq + 2][lrow + 64] = pa1.z;  As[lkq + 3][lrow + 64] = pa1.w;
        *(float4*)&Bs[bk][bnq]     = pb0;
        *(float4*)&Bs[bk + 8][bnq] = pb1;
        __syncthreads();

        const int kn = k0 + 16;
        if (kn < HDIM) {                   // prefetch next tile into registers
            pa0 = *(const float4*)(a0p + kn);
            pa1 = *(const float4*)(a1p + kn);
            pb0 = *(const float4*)(Wx0 + (size_t)(kn + bk)     * HDIM + nbase + bnq);
            pb1 = *(const float4*)(Wx0 + (size_t)(kn + bk + 8) * HDIM + nbase + bnq);
        }

        #pragma unroll
        for (int k = 0; k < 16; k++) {
            float a[8], bb[8];
            *(float4*)&a[0]  = *(const float4*)&As[k][ty * 8];
            *(float4*)&a[4]  = *(const float4*)&As[k][ty * 8 + 4];
            *(float4*)&bb[0] = *(const float4*)&Bs[k][tx * 8];
            *(float4*)&bb[4] = *(const float4*)&Bs[k][tx * 8 + 4];
            #pragma unroll
            for (int r = 0; r < 8; r++)
                #pragma unroll
                for (int c = 0; c < 8; c++)
                    acc[r][c] = fmaf(a[r], bb[c], acc[r][c]);
        }
        __syncthreads();
    }

    #pragma unroll
    for (int r = 0; r < 8; r++) {
        float* orow = g_X1 + (size_t)(mbase + ty * 8 + r) * HDIM + nbase + tx * 8;
        #pragma unroll
        for (int c = 0; c < 8; c++)
            orow[c] = acc[r][c] + b0[nbase + tx * 8 + c];
    }
}

// ===========================================================================
// Kernel 2: persistent sequential recurrence (128 CTAs x 256 threads).
// Per step: h1 = tanh(X1[t] + h1p@Wh0);  h2 = tanh(h1@Wx1 + h2p@Wh1 + b1).
// CTA owns an 8-column slice; thread (m = tid>>2, nq = tid&3) owns 2 columns.
// Two grid barriers per step.
// ===========================================================================
__device__ __forceinline__ void rec_chunk(
    const float* __restrict__ Ag,     // [64][1024] activation, fresh -> __ldcg
    const float* __restrict__ Bg,     // [1024][1024] weight (constant)
    float (&As)[64][132], float (&Bs)[128][8],
    int kc, int nbase, int tid, int m, int nq, float& acc0, float& acc1)
{
    // A chunk: 64 x 128 floats = 2048 float4, 8 per thread, coalesced.
    #pragma unroll
    for (int i = 0; i < 8; i++) {
        int idx = i * 256 + tid;
        int ar  = idx >> 5;
        int ac  = (idx & 31) << 2;
        *(float4*)&As[ar][ac] =
            __ldcg((const float4*)(Ag + (size_t)ar * HDIM + kc + ac));
    }
    // B chunk: 128 x 8 floats = 256 float4, 1 per thread.
    {
        int bk2 = tid >> 1, bq = (tid & 1) << 2;
        *(float4*)&Bs[bk2][bq] =
            *(const float4*)(Bg + (size_t)(kc + bk2) * HDIM + nbase + bq);
    }
    __syncthreads();

    #pragma unroll
    for (int k = 0; k < 128; k += 4) {
        float4 a  = *(const float4*)&As[m][k];
        float2 b0 = *(const float2*)&Bs[k + 0][nq * 2];
        float2 b1 = *(const float2*)&Bs[k + 1][nq * 2];
        float2 b2 = *(const float2*)&Bs[k + 2][nq * 2];
        float2 b3 = *(const float2*)&Bs[k + 3][nq * 2];
        acc0 = fmaf(a.x, b0.x, acc0);  acc1 = fmaf(a.x, b0.y, acc1);
        acc0 = fmaf(a.y, b1.x, acc0);  acc1 = fmaf(a.y, b1.y, acc1);
        acc0 = fmaf(a.z, b2.x, acc0);  acc1 = fmaf(a.z, b2.y, acc1);
        acc0 = fmaf(a.w, b3.x, acc0);  acc1 = fmaf(a.w, b3.y, acc1);
    }
    __syncthreads();
}

__global__ void __launch_bounds__(256) k_rec(
    const float* __restrict__ hidden,   // [2][64][1024]
    const float* __restrict__ Wx,       // [2][1024][1024]
    const float* __restrict__ Wh,       // [2][1024][1024]
    const float* __restrict__ bvec,     // [2][1024]
    float*       __restrict__ out_hf)   // [2][64][1024]
{
    __shared__ float As[64][132];
    __shared__ float Bs[128][8];

    const int tid = threadIdx.x;
    const int cta = blockIdx.x;

    // init ping-pong state: t=0 reads buffer [1]
    for (int i = cta * 256 + tid; i < NB * HDIM; i += NCTA_REC * 256) {
        g_h1[1][i] = hidden[i];
        g_h2[1][i] = hidden[NB * HDIM + i];
    }
    grid_bar();

    const int m     = tid >> 2;           // batch row 0..63
    const int nq    = tid & 3;
    const int nbase = cta * 8;
    const int n0    = nbase + nq * 2;
    const float b1_0 = bvec[HDIM + n0];
    const float b1_1 = bvec[HDIM + n0 + 1];
    const float* Wh0 = Wh;
    const float* Wx1 = Wx + (size_t)HDIM * HDIM;
    const float* Wh1 = Wh + (size_t)HDIM * HDIM;

    for (int t = 0; t < SEQ; t++) {
        const int rp = (t + 1) & 1, wp = t & 1;

        // ---- stage 1: h1 = tanh(X1[t] + h1p @ Wh0) ----
        float acc0 = g_X1[(size_t)(t * NB + m) * HDIM + n0];
        float acc1 = g_X1[(size_t)(t * NB + m) * HDIM + n0 + 1];
        for (int kc = 0; kc < HDIM; kc += 128)
            rec_chunk(g_h1[rp], Wh0, As, Bs, kc, nbase, tid, m, nq, acc0, acc1);
        float h1a = tanhf(acc0), h1b = tanhf(acc1);
        g_h1[wp][m * HDIM + n0]     = h1a;
        g_h1[wp][m * HDIM + n0 + 1] = h1b;
        grid_bar();

        // ---- stage 2: h2 = tanh(h1 @ Wx1 + h2p @ Wh1 + b1) ----
        acc0 = b1_0;  acc1 = b1_1;
        for (int kc = 0; kc < HDIM; kc += 128)
            rec_chunk(g_h1[wp], Wx1, As, Bs, kc, nbase, tid, m, nq, acc0, acc1);
        for (int kc = 0; kc < HDIM; kc += 128)
            rec_chunk(g_h2[rp], Wh1, As, Bs, kc, nbase, tid, m, nq, acc0, acc1);
        float h2a = tanhf(acc0), h2b = tanhf(acc1);
        g_h2[wp][m * HDIM + n0]     = h2a;
        g_h2[wp][m * HDIM + n0 + 1] = h2b;
        g_H2[(size_t)(t * NB + m) * HDIM + n0]     = h2a;
        g_H2[(size_t)(t * NB + m) * HDIM + n0 + 1] = h2b;
        grid_bar();
    }

    // final hidden state: last write was buffer (SEQ-1)&1 == 1
    for (int i = cta * 256 + tid; i < NB * HDIM; i += NCTA_REC * 256) {
        out_hf[i]             = __ldcg(&g_h1[1][i]);
        out_hf[NB * HDIM + i] = __ldcg(&g_h2[1][i]);
    }
}

// ===========================================================================
// Kernel 3:  logits[m][v] = H2[m][:] . fcW[v][:] + fcb[v]
//            M=8192, N=10000, K=1024.  Both operands K-contiguous (NT GEMM).
//            128x128x16 tiles; A and B transposed into smem [k][*].
// ===========================================================================
__global__ void __launch_bounds__(256) k_logits(
    const float* __restrict__ fcW,
    const float* __restrict__ fcb,
    float*       __restrict__ out)
{
    __shared__ float As[16][132];   // [k][m]
    __shared__ float Bs[16][132];   // [k][v]

    const int tid   = threadIdx.x;
    const int mbase = blockIdx.y << 7;
    const int nbase = blockIdx.x << 7;

    const int lrow = tid >> 2;             // 0..63
    const int lkq  = (tid & 3) << 2;       // 0,4,8,12

    const float* a0p = g_H2 + (size_t)(mbase + lrow) * HDIM + lkq;
    const float* a1p = a0p + (size_t)64 * HDIM;
    const int v0 = nbase + lrow, v1 = v0 + 64;
    const bool v0ok = (v0 < VOCAB), v1ok = (v1 < VOCAB);
    const float* b0p = fcW + (size_t)v0 * HDIM + lkq;
    const float* b1p = fcW + (size_t)v1 * HDIM + lkq;

    float4 pa0 = *(const float4*)a0p;
    float4 pa1 = *(const float4*)a1p;
    float4 pb0 = v0ok ? *(const float4*)b0p : make_float4(0.f, 0.f, 0.f, 0.f);
    float4 pb1 = v1ok ? *(const float4*)b1p : make_float4(0.f, 0.f, 0.f, 0.f);

    float acc[8][8];
    #pragma unroll
    for (int r = 0; r < 8; r++)
        #pragma unroll
        for (int c = 0; c < 8; c++) acc[r][c] = 0.f;

    const int tx = tid & 15, ty = tid >> 4;

    for (int k0 = 0; k0 < HDIM; k0 += 16) {
        As[lkq + 0][lrow]      = pa0.x;  As[lkq + 1][lrow]      = pa0.y;
        As[lkq + 2][lrow]      = pa0.z;  As[lkq + 3][lrow]      = pa0.w;
        As[lkq + 0][lrow + 64] = pa1.x;  As[lkq + 1][lrow + 64] = pa1.y;
        As[lkq + 2][lrow + 64] = pa1.z;  As[lkq + 3][lrow + 64] = pa1.w;
        Bs[lkq + 0][lrow]      = pb0.x;  Bs[lkq + 1][lrow]      = pb0.y;
        Bs[lkq + 2][lrow]      = pb0.z;  Bs[lkq + 3][lrow]      = pb0.w;
        Bs[lkq + 0][lrow + 64] = pb1.x;  Bs[lkq + 1][lrow + 64] = pb1.y;
        Bs[lkq + 2][lrow + 64] = pb1.z;  Bs[lkq + 3][lrow + 64] = pb1.w;
        __syncthreads();

        const int kn = k0 + 16;
        if (kn < HDIM) {
            pa0 = *(const float4*)(a0p + kn);
            pa1 = *(const float4*)(a1p + kn);
            pb0 = v0ok ? *(const float4*)(b0p + kn) : make_float4(0.f, 0.f, 0.f, 0.f);
            pb1 = v1ok ? *(const float4*)(b1p + kn) : make_float4(0.f, 0.f, 0.f, 0.f);
        }

        #pragma unroll
        for (int k = 0; k < 16; k++) {
            float a[8], bb[8];
            *(float4*)&a[0]  = *(const float4*)&As[k][ty * 8];
            *(float4*)&a[4]  = *(const float4*)&As[k][ty * 8 + 4];
            *(float4*)&bb[0] = *(const float4*)&Bs[k][tx * 8];
            *(float4*)&bb[4] = *(const float4*)&Bs[k][tx * 8 + 4];
            #pragma unroll
            for (int r = 0; r < 8; r++)
                #pragma unroll
                for (int c = 0; c < 8; c++)
                    acc[r][c] = fmaf(a[r], bb[c], acc[r][c]);
        }
        __syncthreads();
    }

    #pragma unroll
    for (int r = 0; r < 8; r++) {
        const int mrow = mbase + ty * 8 + r;
        float* orow = out + (size_t)mrow * VOCAB + nbase + tx * 8;
        #pragma unroll
        for (int c = 0; c < 8; c++) {
            const int v = nbase + tx * 8 + c;
            if (v < VOCAB) orow[c] = acc[r][c] + fcb[v];
        }
    }
}

// ===========================================================================
extern "C" void kernel_launch(void* const* d_in, const int* in_sizes, int n_in,
                              void* d_out, int out_size)
{
    const int*   tok    = (const int*)  d_in[0];   // [128][64] int32
    const float* hidden = (const float*)d_in[1];   // [2][64][1024]
    const float* emb    = (const float*)d_in[2];   // [10000][1024]
    const float* Wx     = (const float*)d_in[3];   // [2][1024][1024]
    const float* Wh     = (const float*)d_in[4];   // [2][1024][1024]
    const float* bvec   = (const float*)d_in[5];   // [2][1024]
    const float* fcW    = (const float*)d_in[6];   // [10000][1024]
    const float* fcb    = (const float*)d_in[7];   // [10000]
    float* out = (float*)d_out;                    // logits [128*64*10000] ++ h_final [2*64*1024]

    (void)in_sizes; (void)n_in; (void)out_size;

    // 1) X1 = emb[tok] @ Wx0 + b0
    dim3 g1(HDIM / 128, M1 / 128);                 // (8, 64)
    k_x1<<<g1, 256>>>(tok, emb, Wx, bvec);

    // 2) sequential recurrence -> g_H2, h_final tail of out
    k_rec<<<NCTA_REC, 256>>>(hidden, Wx, Wh, bvec,
                             out + (size_t)M1 * VOCAB);

    // 3) logits = H2 @ fcW^T + fcb
    dim3 g3((VOCAB + 127) / 128, M1 / 128);        // (79, 64)
    k_logits<<<g3, 256>>>(fcW, fcb, out);
}

// round 7
// speedup vs baseline: 1.0008x; 1.0008x over previous
#include <cuda_runtime.h>
#include <math.h>
#include <stdint.h>

#define SEQ    128
#define NB     64
#define VOCAB  10000
#define HDIM   1024
#define M1     (SEQ * NB)          /* 8192 */
#define NCTA_REC 128

// ---------------- static device scratch (no allocation allowed) ------------
__device__ float g_X1[(size_t)M1 * HDIM];      // emb[tok]@Wx0 + b0 for all steps (32 MB)
__device__ float g_H2[(size_t)M1 * HDIM];      // layer-2 hidden trajectory (32 MB)
__device__ float g_h1[2][NB * HDIM];           // ping-pong layer-1 state
__device__ float g_h2[2][NB * HDIM];           // ping-pong layer-2 state
__device__ unsigned g_bar_count;
__device__ volatile unsigned g_bar_gen;

// ---------------- grid-wide barrier (all 128 CTAs resident) ----------------
__device__ __forceinline__ void grid_bar() {
    __threadfence();                       // publish this thread's global writes
    __syncthreads();
    if (threadIdx.x == 0) {
        unsigned gen = g_bar_gen;
        if (atomicAdd(&g_bar_count, 1u) == NCTA_REC - 1) {
            g_bar_count = 0;
            __threadfence();
            g_bar_gen = gen + 1;           // release
        } else {
            while (g_bar_gen == gen) { __nanosleep(40); }
            __threadfence();               // acquire: invalidate L1 before consuming
        }
    }
    __syncthreads();
}

// ===========================================================================
// Kernel 1:  X1[m][n] = emb[tok[m]][:] @ Wx0[:][n] + b0[n]
//            M=8192, N=1024, K=1024.  128x128x16 tiles, 256 thr, 8x8 micro.
//            A (emb rows) is K-contiguous -> transposed into smem [k][m].
//            B (Wx0) is [k][n] row-major -> stored directly.
// ===========================================================================
__global__ void __launch_bounds__(256) k_x1(
    const int*   __restrict__ tok,
    const float* __restrict__ emb,
    const float* __restrict__ Wx0,
    const float* __restrict__ b0)
{
    __shared__ float As[16][132];   // [k][m]
    __shared__ float Bs[16][132];   // [k][n]
    __shared__ int   stok[128];

    const int tid   = threadIdx.x;
    const int mbase = blockIdx.y << 7;
    const int nbase = blockIdx.x << 7;

    if (tid < 128) stok[tid] = tok[mbase + tid];
    __syncthreads();

    const int lrow = tid >> 2;             // 0..63  (A rows lrow, lrow+64)
    const int lkq  = (tid & 3) << 2;       // 0,4,8,12
    const int bk   = tid >> 5;             // 0..7   (B rows bk, bk+8)
    const int bnq  = (tid & 31) << 2;      // 0..124

    const float* a0p = emb + (size_t)stok[lrow]      * HDIM + lkq;
    const float* a1p = emb + (size_t)stok[lrow + 64] * HDIM + lkq;

    float acc[8][8];
    #pragma unroll
    for (int r = 0; r < 8; r++)
        #pragma unroll
        for (int c = 0; c < 8; c++) acc[r][c] = 0.f;

    float4 pa0 = *(const float4*)a0p;
    float4 pa1 = *(const float4*)a1p;
    float4 pb0 = *(const float4*)(Wx0 + (size_t)bk       * HDIM + nbase + bnq);
    float4 pb1 = *(const float4*)(Wx0 + (size_t)(bk + 8) * HDIM + nbase + bnq);

    const int tx = tid & 15, ty = tid >> 4;

    for (int k0 = 0; k0 < HDIM; k0 += 16) {
        As[lkq + 0][lrow]      = pa0.x;  As[lkq + 1][lrow]      = pa0.y;
        As[lkq + 2][lrow]      = pa0.z;  As[lkq + 3][lrow]      = pa0.w;
        As[lkq + 0][lrow + 64] = pa1.x;  As[lkq + 1][lrow + 64] = pa1.y;
        As[lkq + 2][lrow + 64] = pa1.z;  As[lkq + 3][lrow + 64] = pa1.w;
        *(float4*)&Bs[bk][bnq]     = pb0;
        *(float4*)&Bs[bk + 8][bnq] = pb1;
        __syncthreads();

        const int kn = k0 + 16;
        if (kn < HDIM) {                   // prefetch next tile into registers
            pa0 = *(const float4*)(a0p + kn);
            pa1 = *(const float4*)(a1p + kn);
            pb0 = *(const float4*)(Wx0 + (size_t)(kn + bk)     * HDIM + nbase + bnq);
            pb1 = *(const float4*)(Wx0 + (size_t)(kn + bk + 8) * HDIM + nbase + bnq);
        }

        #pragma unroll
        for (int k = 0; k < 16; k++) {
            float a[8], bb[8];
            *(float4*)&a[0]  = *(const float4*)&As[k][ty * 8];
            *(float4*)&a[4]  = *(const float4*)&As[k][ty * 8 + 4];
            *(float4*)&bb[0] = *(const float4*)&Bs[k][tx * 8];
            *(float4*)&bb[4] = *(const float4*)&Bs[k][tx * 8 + 4];
            #pragma unroll
            for (int r = 0; r < 8; r++)
                #pragma unroll
                for (int c = 0; c < 8; c++)
                    acc[r][c] = fmaf(a[r], bb[c], acc[r][c]);
        }
        __syncthreads();
    }

    #pragma unroll
    for (int r = 0; r < 8; r++) {
        float* orow = g_X1 + (size_t)(mbase + ty * 8 + r) * HDIM + nbase + tx * 8;
        #pragma unroll
        for (int c = 0; c < 8; c++)
            orow[c] = acc[r][c] + b0[nbase + tx * 8 + c];
    }
}

// ===========================================================================
// Kernel 2: persistent sequential recurrence (128 CTAs x 256 threads).
// Per step: h1 = tanh(X1[t] + h1p@Wh0);  h2 = tanh(h1@Wx1 + h2p@Wh1 + b1).
// CTA owns an 8-column slice; thread (m = tid>>2, nq = tid&3) owns 2 columns.
// Two grid barriers per step.
// ===========================================================================
__device__ __forceinline__ void rec_chunk(
    const float* __restrict__ Ag,     // [64][1024] activation, fresh -> __ldcg
    const float* __restrict__ Bg,     // [1024][1024] weight (constant)
    float (&As)[64][132], float (&Bs)[128][8],
    int kc, int nbase, int tid, int m, int nq, float& acc0, float& acc1)
{
    // A chunk: 64 x 128 floats = 2048 float4, 8 per thread, coalesced.
    #pragma unroll
    for (int i = 0; i < 8; i++) {
        int idx = i * 256 + tid;
        int ar  = idx >> 5;
        int ac  = (idx & 31) << 2;
        *(float4*)&As[ar][ac] =
            __ldcg((const float4*)(Ag + (size_t)ar * HDIM + kc + ac));
    }
    // B chunk: 128 x 8 floats = 256 float4, 1 per thread.
    {
        int bk2 = tid >> 1, bq = (tid & 1) << 2;
        *(float4*)&Bs[bk2][bq] =
            *(const float4*)(Bg + (size_t)(kc + bk2) * HDIM + nbase + bq);
    }
    __syncthreads();

    #pragma unroll
    for (int k = 0; k < 128; k += 4) {
        float4 a  = *(const float4*)&As[m][k];
        float2 b0 = *(const float2*)&Bs[k + 0][nq * 2];
        float2 b1 = *(const float2*)&Bs[k + 1][nq * 2];
        float2 b2 = *(const float2*)&Bs[k + 2][nq * 2];
        float2 b3 = *(const float2*)&Bs[k + 3][nq * 2];
        acc0 = fmaf(a.x, b0.x, acc0);  acc1 = fmaf(a.x, b0.y, acc1);
        acc0 = fmaf(a.y, b1.x, acc0);  acc1 = fmaf(a.y, b1.y, acc1);
        acc0 = fmaf(a.z, b2.x, acc0);  acc1 = fmaf(a.z, b2.y, acc1);
        acc0 = fmaf(a.w, b3.x, acc0);  acc1 = fmaf(a.w, b3.y, acc1);
    }
    __syncthreads();
}

__global__ void __launch_bounds__(256) k_rec(
    const float* __restrict__ hidden,   // [2][64][1024]
    const float* __restrict__ Wx,       // [2][1024][1024]
    const float* __restrict__ Wh,       // [2][1024][1024]
    const float* __restrict__ bvec,     // [2][1024]
    float*       __restrict__ out_hf)   // [2][64][1024]
{
    __shared__ float As[64][132];
    __shared__ float Bs[128][8];

    const int tid = threadIdx.x;
    const int cta = blockIdx.x;

    // init ping-pong state: t=0 reads buffer [1]
    for (int i = cta * 256 + tid; i < NB * HDIM; i += NCTA_REC * 256) {
        g_h1[1][i] = hidden[i];
        g_h2[1][i] = hidden[NB * HDIM + i];
    }
    grid_bar();

    const int m     = tid >> 2;           // batch row 0..63
    const int nq    = tid & 3;
    const int nbase = cta * 8;
    const int n0    = nbase + nq * 2;
    const float b1_0 = bvec[HDIM + n0];
    const float b1_1 = bvec[HDIM + n0 + 1];
    const float* Wh0 = Wh;
    const float* Wx1 = Wx + (size_t)HDIM * HDIM;
    const float* Wh1 = Wh + (size_t)HDIM * HDIM;

    for (int t = 0; t < SEQ; t++) {
        const int rp = (t + 1) & 1, wp = t & 1;

        // ---- stage 1: h1 = tanh(X1[t] + h1p @ Wh0) ----
        float acc0 = g_X1[(size_t)(t * NB + m) * HDIM + n0];
        float acc1 = g_X1[(size_t)(t * NB + m) * HDIM + n0 + 1];
        for (int kc = 0; kc < HDIM; kc += 128)
            rec_chunk(g_h1[rp], Wh0, As, Bs, kc, nbase, tid, m, nq, acc0, acc1);
        float h1a = tanhf(acc0), h1b = tanhf(acc1);
        g_h1[wp][m * HDIM + n0]     = h1a;
        g_h1[wp][m * HDIM + n0 + 1] = h1b;
        grid_bar();

        // ---- stage 2: h2 = tanh(h1 @ Wx1 + h2p @ Wh1 + b1) ----
        acc0 = b1_0;  acc1 = b1_1;
        for (int kc = 0; kc < HDIM; kc += 128)
            rec_chunk(g_h1[wp], Wx1, As, Bs, kc, nbase, tid, m, nq, acc0, acc1);
        for (int kc = 0; kc < HDIM; kc += 128)
            rec_chunk(g_h2[rp], Wh1, As, Bs, kc, nbase, tid, m, nq, acc0, acc1);
        float h2a = tanhf(acc0), h2b = tanhf(acc1);
        g_h2[wp][m * HDIM + n0]     = h2a;
        g_h2[wp][m * HDIM + n0 + 1] = h2b;
        g_H2[(size_t)(t * NB + m) * HDIM + n0]     = h2a;
        g_H2[(size_t)(t * NB + m) * HDIM + n0 + 1] = h2b;
        grid_bar();
    }

    // final hidden state: last write was buffer (SEQ-1)&1 == 1
    for (int i = cta * 256 + tid; i < NB * HDIM; i += NCTA_REC * 256) {
        out_hf[i]             = __ldcg(&g_h1[1][i]);
        out_hf[NB * HDIM + i] = __ldcg(&g_h2[1][i]);
    }
}

// ===========================================================================
// Kernel 3:  logits[m][v] = H2[m][:] . fcW[v][:] + fcb[v]
//            M=8192, N=10000, K=1024.  Both operands K-contiguous (NT GEMM).
//            128x128x16 tiles; A and B transposed into smem [k][*].
// ===========================================================================
__global__ void __launch_bounds__(256) k_logits(
    const float* __restrict__ fcW,
    const float* __restrict__ fcb,
    float*       __restrict__ out)
{
    __shared__ float As[16][132];   // [k][m]
    __shared__ float Bs[16][132];   // [k][v]

    const int tid   = threadIdx.x;
    const int mbase = blockIdx.y << 7;
    const int nbase = blockIdx.x << 7;

    const int lrow = tid >> 2;             // 0..63
    const int lkq  = (tid & 3) << 2;       // 0,4,8,12

    const float* a0p = g_H2 + (size_t)(mbase + lrow) * HDIM + lkq;
    const float* a1p = a0p + (size_t)64 * HDIM;
    const int v0 = nbase + lrow, v1 = v0 + 64;
    const bool v0ok = (v0 < VOCAB), v1ok = (v1 < VOCAB);
    const float* b0p = fcW + (size_t)v0 * HDIM + lkq;
    const float* b1p = fcW + (size_t)v1 * HDIM + lkq;

    float4 pa0 = *(const float4*)a0p;
    float4 pa1 = *(const float4*)a1p;
    float4 pb0 = v0ok ? *(const float4*)b0p : make_float4(0.f, 0.f, 0.f, 0.f);
    float4 pb1 = v1ok ? *(const float4*)b1p : make_float4(0.f, 0.f, 0.f, 0.f);

    float acc[8][8];
    #pragma unroll
    for (int r = 0; r < 8; r++)
        #pragma unroll
        for (int c = 0; c < 8; c++) acc[r][c] = 0.f;

    const int tx = tid & 15, ty = tid >> 4;

    for (int k0 = 0; k0 < HDIM; k0 += 16) {
        As[lkq + 0][lrow]      = pa0.x;  As[lkq + 1][lrow]      = pa0.y;
        As[lkq + 2][lrow]      = pa0.z;  As[lkq + 3][lrow]      = pa0.w;
        As[lkq + 0][lrow + 64] = pa1.x;  As[lkq + 1][lrow + 64] = pa1.y;
        As[lkq + 2][lrow + 64] = pa1.z;  As[lkq + 3][lrow + 64] = pa1.w;
        Bs[lkq + 0][lrow]      = pb0.x;  Bs[lkq + 1][lrow]      = pb0.y;
        Bs[lkq + 2][lrow]      = pb0.z;  Bs[lkq + 3][lrow]      = pb0.w;
        Bs[lkq + 0][lrow + 64] = pb1.x;  Bs[lkq + 1][lrow + 64] = pb1.y;
        Bs[lkq + 2][lrow + 64] = pb1.z;  Bs[lkq + 3][lrow + 64] = pb1.w;
        __syncthreads();

        const int kn = k0 + 16;
        if (kn < HDIM) {
            pa0 = *(const float4*)(a0p + kn);
            pa1 = *(const float4*)(a1p + kn);
            pb0 = v0ok ? *(const float4*)(b0p + kn) : make_float4(0.f, 0.f, 0.f, 0.f);
            pb1 = v1ok ? *(const float4*)(b1p + kn) : make_float4(0.f, 0.f, 0.f, 0.f);
        }

        #pragma unroll
        for (int k = 0; k < 16; k++) {
            float a[8], bb[8];
            *(float4*)&a[0]  = *(const float4*)&As[k][ty * 8];
            *(float4*)&a[4]  = *(const float4*)&As[k][ty * 8 + 4];
            *(float4*)&bb[0] = *(const float4*)&Bs[k][tx * 8];
            *(float4*)&bb[4] = *(const float4*)&Bs[k][tx * 8 + 4];
            #pragma unroll
            for (int r = 0; r < 8; r++)
                #pragma unroll
                for (int c = 0; c < 8; c++)
                    acc[r][c] = fmaf(a[r], bb[c], acc[r][c]);
        }
        __syncthreads();
    }

    #pragma unroll
    for (int r = 0; r < 8; r++) {
        const int mrow = mbase + ty * 8 + r;
        float* orow = out + (size_t)mrow * VOCAB + nbase + tx * 8;
        #pragma unroll
        for (int c = 0; c < 8; c++) {
            const int v = nbase + tx * 8 + c;
            if (v < VOCAB) orow[c] = acc[r][c] + fcb[v];
        }
    }
}

// ===========================================================================
extern "C" void kernel_launch(void* const* d_in, const int* in_sizes, int n_in,
                              void* d_out, int out_size)
{
    const int*   tok    = (const int*)  d_in[0];   // [128][64] int32
    const float* hidden = (const float*)d_in[1];   // [2][64][1024]
    const float* emb    = (const float*)d_in[2];   // [10000][1024]
    const float* Wx     = (const float*)d_in[3];   // [2][1024][1024]
    const float* Wh     = (const float*)d_in[4];   // [2][1024][1024]
    const float* bvec   = (const float*)d_in[5];   // [2][1024]
    const float* fcW    = (const float*)d_in[6];   // [10000][1024]
    const float* fcb    = (const float*)d_in[7];   // [10000]
    float* out = (float*)d_out;                    // logits [128*64*10000] ++ h_final [2*64*1024]

    (void)in_sizes; (void)n_in; (void)out_size;

    // 1) X1 = emb[tok] @ Wx0 + b0
    dim3 g1(HDIM / 128, M1 / 128);                 // (8, 64)
    k_x1<<<g1, 256>>>(tok, emb, Wx, bvec);

    // 2) sequential recurrence -> g_H2, h_final tail of out
    k_rec<<<NCTA_REC, 256>>>(hidden, Wx, Wh, bvec,
                             out + (size_t)M1 * VOCAB);

    // 3) logits = H2 @ fcW^T + fcb
    dim3 g3((VOCAB + 127) / 128, M1 / 128);        // (79, 64)
    k_logits<<<g3, 256>>>(fcW, fcb, out);
}